// round 1
// baseline (speedup 1.0000x reference)
#include <cuda_runtime.h>
#include <cstdint>

// VanillaRNN: p = (scan_t h = tanh(x_t @ Whx + h @ Whh + bh)) @ Wph + bp
// B=256, T=1024, D=64, H=512, C=10, all fp32.
//
// Strategy (round 1): single persistent kernel, 128 co-resident blocks.
//  - Whx/Whh column-slice resident in SMEM per block (576x64 fp32).
//  - Per step: stage [x_t | h_prev] in SMEM (duplicated pairs for f32x2 FMA),
//    each block computes a 16-row x 64-col tile of h_new, tanh, store to a
//    double-buffered __device__ h array, then a grid-wide atomic barrier.
//  - After the loop, col-tile-0 blocks compute the final 256x10 projection.

#define SEQ_LEN   1024
#define IN_DIM    64
#define HID       512
#define NCLS      10
#define BATCH     256
#define KTOT      (IN_DIM + HID)   // 576

#define COL_TILES 8
#define ROW_TILES 16
#define GRID_DIM  (COL_TILES * ROW_TILES)  // 128 blocks (<=148 SMs, 1 CTA/SM)
#define NTHREADS  128
#define TILE_C    64
#define TILE_R    16

#define SV_PITCH  18   // float2 entries per k row (pad: keeps 16B alignment, spreads banks)

// SMEM layout (dynamic):
//   sW : [KTOT][TILE_C] float      = 147456 B
//   sV : [KTOT][SV_PITCH] float2   =  82944 B   (value duplicated in .x/.y)
#define SW_BYTES  (KTOT * TILE_C * 4)
#define SV_BYTES  (KTOT * SV_PITCH * 8)
#define SMEM_BYTES (SW_BYTES + SV_BYTES)   // 230400 <= 232448 (sm_103a max dyn)

__device__ float    g_h[2][BATCH][HID];   // double-buffered hidden state
__device__ unsigned g_bar;                // monotonic barrier counter

__device__ __forceinline__ unsigned long long packxy(float x, float y) {
    unsigned long long r;
    asm("mov.b64 %0, {%1, %2};" : "=l"(r) : "f"(x), "f"(y));
    return r;
}
__device__ __forceinline__ float2 unpk(unsigned long long v) {
    float2 f;
    asm("mov.b64 {%0, %1}, %2;" : "=f"(f.x), "=f"(f.y) : "l"(v));
    return f;
}
__device__ __forceinline__ void fma2(unsigned long long& d,
                                     unsigned long long a,
                                     unsigned long long b) {
    asm("fma.rn.f32x2 %0, %1, %2, %0;" : "+l"(d) : "l"(a), "l"(b));
}

__global__ void __launch_bounds__(NTHREADS, 1)
rnn_persistent_kernel(const float* __restrict__ x,
                      const float* __restrict__ Whx,
                      const float* __restrict__ Whh,
                      const float* __restrict__ Wph,
                      const float* __restrict__ bh,
                      const float* __restrict__ bp,
                      float* __restrict__ out)
{
    extern __shared__ unsigned char smem[];
    float*  sW = reinterpret_cast<float*>(smem);                 // [KTOT][TILE_C]
    float2* sV = reinterpret_cast<float2*>(smem + SW_BYTES);     // [KTOT][SV_PITCH]

    const int tid = threadIdx.x;
    const int bid = blockIdx.x;
    const int jt  = bid & (COL_TILES - 1);   // col tile
    const int it  = bid >> 3;                // row tile
    const int c0  = jt * TILE_C;
    const int r0  = it * TILE_R;

    // ---- one-time: load combined W slice [Whx; Whh][:, c0:c0+64] ----
    for (int idx = tid; idx < KTOT * TILE_C; idx += NTHREADS) {
        int k = idx / TILE_C;
        int c = idx - k * TILE_C;
        float w = (k < IN_DIM) ? Whx[k * HID + c0 + c]
                               : Whh[(k - IN_DIM) * HID + c0 + c];
        sW[k * TILE_C + c] = w;
    }

    // thread tiling: 2 rows x 4 cols per thread
    const int r4 = tid & 7;     // row-pair index: rows 2*r4, 2*r4+1
    const int cq = tid >> 3;    // col-quad index: cols 4*cq .. 4*cq+3

    // per-thread bias (cols fixed for whole run)
    const float bb0 = bh[c0 + 4 * cq + 0];
    const float bb1 = bh[c0 + 4 * cq + 1];
    const float bb2 = bh[c0 + 4 * cq + 2];
    const float bb3 = bh[c0 + 4 * cq + 3];
    const unsigned long long bias01 = packxy(bb0, bb1);
    const unsigned long long bias23 = packxy(bb2, bb3);

    __syncthreads();

    const float* wp = sW + 4 * cq;           // + k*TILE_C per k
    const float2* vp = sV + 2 * r4;          // + k*SV_PITCH per k

    for (int t = 0; t < SEQ_LEN; ++t) {
        const float* hb = &g_h[t & 1][0][0];

        // ---- stage v = [x_t(rows) | h_prev(rows)] as duplicated pairs ----
        for (int idx = tid; idx < TILE_R * IN_DIM; idx += NTHREADS) {
            int r = idx >> 6;           // 0..15
            int k = idx & 63;           // 0..63
            float v = x[(size_t)(r0 + r) * (SEQ_LEN * IN_DIM) + (size_t)t * IN_DIM + k];
            sV[k * SV_PITCH + r] = make_float2(v, v);
        }
        for (int idx = tid; idx < TILE_R * HID; idx += NTHREADS) {
            int r = idx >> 9;           // 0..15
            int k = idx & 511;          // 0..511
            float v = __ldcv(hb + (r0 + r) * HID + k);  // bypass (possibly stale) L1
            sV[(IN_DIM + k) * SV_PITCH + r] = make_float2(v, v);
        }
        __syncthreads();

        // ---- main GEMM tile: acc[2 rows][4 cols], K = 576 ----
        unsigned long long a00 = bias01, a01 = bias23;  // row 2*r4
        unsigned long long a10 = bias01, a11 = bias23;  // row 2*r4+1

        #pragma unroll 8
        for (int k = 0; k < KTOT; ++k) {
            longlong2 w = *reinterpret_cast<const longlong2*>(wp + k * TILE_C);
            longlong2 v = *reinterpret_cast<const longlong2*>(vp + k * SV_PITCH);
            unsigned long long w01 = (unsigned long long)w.x;
            unsigned long long w23 = (unsigned long long)w.y;
            unsigned long long v0  = (unsigned long long)v.x;  // {h_r0, h_r0}
            unsigned long long v1  = (unsigned long long)v.y;  // {h_r1, h_r1}
            fma2(a00, v0, w01);
            fma2(a01, v0, w23);
            fma2(a10, v1, w01);
            fma2(a11, v1, w23);
        }

        // ---- epilogue: tanh + store to other buffer ----
        float2 p00 = unpk(a00), p01 = unpk(a01);
        float2 p10 = unpk(a10), p11 = unpk(a11);
        float4 o0, o1;
        o0.x = tanhf(p00.x); o0.y = tanhf(p00.y); o0.z = tanhf(p01.x); o0.w = tanhf(p01.y);
        o1.x = tanhf(p10.x); o1.y = tanhf(p10.y); o1.z = tanhf(p11.x); o1.w = tanhf(p11.y);

        float* hn = &g_h[(t + 1) & 1][0][0];
        *reinterpret_cast<float4*>(hn + (r0 + 2 * r4)     * HID + c0 + 4 * cq) = o0;
        *reinterpret_cast<float4*>(hn + (r0 + 2 * r4 + 1) * HID + c0 + 4 * cq) = o1;

        // ---- grid barrier (release: fence+arrive, acquire: spin+fence) ----
        __threadfence();
        __syncthreads();
        if (tid == 0) {
            atomicAdd(&g_bar, 1u);
            const unsigned target = (unsigned)(t + 1) * GRID_DIM;
            while (*(volatile unsigned*)&g_bar < target) {
                __nanosleep(64);
            }
            __threadfence();
        }
        __syncthreads();
    }

    // ---- final projection p = h_final @ Wph + bp (col-tile-0 blocks only) ----
    if (jt == 0) {
        float* sP = reinterpret_cast<float*>(smem);           // [HID][NCLS]
        float* sH = reinterpret_cast<float*>(smem) + HID * NCLS; // [TILE_R][HID]

        for (int idx = tid; idx < HID * NCLS; idx += NTHREADS)
            sP[idx] = Wph[idx];
        const float* hf = &g_h[SEQ_LEN & 1][0][0];
        for (int idx = tid; idx < TILE_R * HID; idx += NTHREADS) {
            int r = idx >> 9;
            int k = idx & 511;
            sH[r * HID + k] = __ldcv(hf + (r0 + r) * HID + k);
        }
        __syncthreads();

        for (int idx = tid; idx < TILE_R * NCLS; idx += NTHREADS) {
            int r = idx / NCLS;
            int c = idx - r * NCLS;
            float s = bp[c];
            const float* hr = sH + r * HID;
            #pragma unroll 8
            for (int k = 0; k < HID; ++k)
                s += hr[k] * sP[k * NCLS + c];
            out[(r0 + r) * NCLS + c] = s;
        }
    }
}

extern "C" void kernel_launch(void* const* d_in, const int* in_sizes, int n_in,
                              void* d_out, int out_size)
{
    const float* x   = (const float*)d_in[0];
    const float* Whx = (const float*)d_in[1];
    const float* Whh = (const float*)d_in[2];
    const float* Wph = (const float*)d_in[3];
    const float* bh  = (const float*)d_in[4];
    const float* bp  = (const float*)d_in[5];
    float* out = (float*)d_out;

    // Reset barrier counter and zero the initial hidden-state buffer every
    // launch (graph replays included) — keeps the kernel deterministic.
    void* bar_addr = nullptr;
    void* h_addr   = nullptr;
    cudaGetSymbolAddress(&bar_addr, g_bar);
    cudaGetSymbolAddress(&h_addr, g_h);
    cudaMemsetAsync(bar_addr, 0, sizeof(unsigned));
    cudaMemsetAsync(h_addr, 0, (size_t)BATCH * HID * sizeof(float));  // g_h[0]

    cudaFuncSetAttribute(rnn_persistent_kernel,
                         cudaFuncAttributeMaxDynamicSharedMemorySize, SMEM_BYTES);

    rnn_persistent_kernel<<<GRID_DIM, NTHREADS, SMEM_BYTES>>>(
        x, Whx, Whh, Wph, bh, bp, out);
}

// round 2
// speedup vs baseline: 1.2298x; 1.2298x over previous
#include <cuda_runtime.h>
#include <cstdint>

// VanillaRNN: p = (scan_t h = tanh(x_t @ Whx + h @ Whh + bh)) @ Wph + bp
// B=256, T=1024, D=64, H=512, C=10, all fp32.
//
// Round 2: persistent kernel, 128 blocks x 512 threads, split-K(4) per block.
//  - W slice (576x64) resident in SMEM per block.
//  - Per step: stage [x_t | h_prev] (dup pairs for f32x2 FMA), 4 K-groups of
//    128 threads each compute partial 16x64 tile over K-chunk=144, SMEM
//    reduction + bias + tanh, store to double-buffered global h, grid barrier.

#define SEQ_LEN   1024
#define IN_DIM    64
#define HID       512
#define NCLS      10
#define BATCH     256
#define KTOT      (IN_DIM + HID)   // 576

#define COL_TILES 8
#define ROW_TILES 16
#define GRID_DIM  (COL_TILES * ROW_TILES)  // 128 blocks, 1 CTA/SM
#define NTHREADS  512
#define KGROUPS   4
#define KCHUNK    (KTOT / KGROUPS)         // 144
#define TILE_C    64
#define TILE_R    16

#define SV_PITCH  18   // float2 per k row (pad: 16B align + bank spread)

// SMEM layout (dynamic):
//   sW : [KTOT][TILE_C] float      = 147456 B
//   sV : [KTOT][SV_PITCH] float2   =  82944 B (value duplicated .x/.y)
//        (reused as reduction scratch float2[4][512] = 16 KB between steps)
//   sB : [TILE_C] float            =    256 B
#define SW_BYTES  (KTOT * TILE_C * 4)
#define SV_BYTES  (KTOT * SV_PITCH * 8)
#define SMEM_BYTES (SW_BYTES + SV_BYTES + TILE_C * 4)   // 230656

__device__ float    g_h[2][BATCH][HID];   // double-buffered hidden state
__device__ unsigned g_bar;                // monotonic barrier counter

__device__ __forceinline__ float2 unpk(unsigned long long v) {
    float2 f;
    asm("mov.b64 {%0, %1}, %2;" : "=f"(f.x), "=f"(f.y) : "l"(v));
    return f;
}
__device__ __forceinline__ void fma2(unsigned long long& d,
                                     unsigned long long a,
                                     unsigned long long b) {
    asm("fma.rn.f32x2 %0, %1, %2, %0;" : "+l"(d) : "l"(a), "l"(b));
}

__global__ void __launch_bounds__(NTHREADS, 1)
rnn_persistent_kernel(const float* __restrict__ x,
                      const float* __restrict__ Whx,
                      const float* __restrict__ Whh,
                      const float* __restrict__ Wph,
                      const float* __restrict__ bh,
                      const float* __restrict__ bp,
                      float* __restrict__ out)
{
    extern __shared__ unsigned char smem[];
    float*  sW   = reinterpret_cast<float*>(smem);               // [KTOT][64]
    float2* sV   = reinterpret_cast<float2*>(smem + SW_BYTES);   // [KTOT][18]
    float2* sRed = sV;                                           // [4][512] reuse
    float*  sB   = reinterpret_cast<float*>(smem + SW_BYTES + SV_BYTES); // [64]

    const int tid = threadIdx.x;
    const int bid = blockIdx.x;
    const int jt  = bid & (COL_TILES - 1);   // col tile
    const int it  = bid >> 3;                // row tile
    const int c0  = jt * TILE_C;
    const int r0  = it * TILE_R;

    // ---- one-time: load combined W slice [Whx; Whh][:, c0:c0+64] + bias ----
    for (int idx = tid; idx < KTOT * TILE_C; idx += NTHREADS) {
        int k = idx / TILE_C;
        int c = idx - k * TILE_C;
        float w = (k < IN_DIM) ? Whx[k * HID + c0 + c]
                               : Whh[(k - IN_DIM) * HID + c0 + c];
        sW[k * TILE_C + c] = w;
    }
    if (tid < TILE_C) sB[tid] = bh[c0 + tid];

    // split-K thread org: 4 groups of 128 threads; within a group 2r x 4c
    const int kg = tid >> 7;                 // 0..3
    const int pg = tid & 127;
    const int r4 = pg & 7;                   // rows 2*r4, 2*r4+1
    const int cq = pg >> 3;                  // cols 4*cq..4*cq+3
    const int k0 = kg * KCHUNK;

    __syncthreads();

    const float*  wp = sW + 4 * cq;          // + k*TILE_C
    const float2* vp = sV + 2 * r4;          // + k*SV_PITCH

    // reduction mapping: this thread finalizes output pair p = tid (p<512)
    const int rcp  = tid & 31;               // colpair 0..31
    const int rrow = tid >> 5;               // row 0..15

    for (int t = 0; t < SEQ_LEN; ++t) {
        const float* hb = &g_h[t & 1][0][0];

        // ---- stage v = [x_t | h_prev] as duplicated pairs ----
        for (int idx = tid; idx < TILE_R * IN_DIM; idx += NTHREADS) {
            int r = idx >> 6;
            int k = idx & 63;
            float v = x[(size_t)(r0 + r) * (SEQ_LEN * IN_DIM) + (size_t)t * IN_DIM + k];
            sV[k * SV_PITCH + r] = make_float2(v, v);
        }
        for (int idx = tid; idx < TILE_R * HID; idx += NTHREADS) {
            int r = idx >> 9;
            int k = idx & 511;
            float v = __ldcv(hb + (r0 + r) * HID + k);  // fresh (bypass L1)
            sV[(IN_DIM + k) * SV_PITCH + r] = make_float2(v, v);
        }
        __syncthreads();

        // ---- partial GEMM tile over this group's K-chunk ----
        unsigned long long a00 = 0, a01 = 0;   // row 2*r4,   colpairs 2cq,2cq+1
        unsigned long long a10 = 0, a11 = 0;   // row 2*r4+1
        #pragma unroll 8
        for (int k = k0; k < k0 + KCHUNK; ++k) {
            longlong2 w = *reinterpret_cast<const longlong2*>(wp + k * TILE_C);
            longlong2 v = *reinterpret_cast<const longlong2*>(vp + k * SV_PITCH);
            unsigned long long w01 = (unsigned long long)w.x;
            unsigned long long w23 = (unsigned long long)w.y;
            unsigned long long v0  = (unsigned long long)v.x;
            unsigned long long v1  = (unsigned long long)v.y;
            fma2(a00, v0, w01);
            fma2(a01, v0, w23);
            fma2(a10, v1, w01);
            fma2(a11, v1, w23);
        }
        __syncthreads();   // sV reads done; safe to reuse as sRed

        // ---- write partials: sRed[kg][row*32 + colpair] ----
        {
            float2* rb = sRed + kg * 512;
            rb[(2 * r4)     * 32 + 2 * cq    ] = unpk(a00);
            rb[(2 * r4)     * 32 + 2 * cq + 1] = unpk(a01);
            rb[(2 * r4 + 1) * 32 + 2 * cq    ] = unpk(a10);
            rb[(2 * r4 + 1) * 32 + 2 * cq + 1] = unpk(a11);
        }
        __syncthreads();

        // ---- reduce 4 partials + bias + tanh + store h_new ----
        {
            float2 s0 = sRed[tid];
            float2 s1 = sRed[512 + tid];
            float2 s2 = sRed[1024 + tid];
            float2 s3 = sRed[1536 + tid];
            float sx = (s0.x + s1.x) + (s2.x + s3.x) + sB[2 * rcp];
            float sy = (s0.y + s1.y) + (s2.y + s3.y) + sB[2 * rcp + 1];
            float2 o = make_float2(tanhf(sx), tanhf(sy));
            float* hn = &g_h[(t + 1) & 1][0][0];
            *reinterpret_cast<float2*>(hn + (r0 + rrow) * HID + c0 + 2 * rcp) = o;
        }

        // ---- grid barrier ----
        __threadfence();
        __syncthreads();
        if (tid == 0) {
            atomicAdd(&g_bar, 1u);
            const unsigned target = (unsigned)(t + 1) * GRID_DIM;
            while (*(volatile unsigned*)&g_bar < target) { }
            __threadfence();
        }
        __syncthreads();
    }

    // ---- final projection p = h_final @ Wph + bp (col-tile-0 blocks) ----
    if (jt == 0) {
        float* sP = reinterpret_cast<float*>(smem);                 // [512][10]
        float* sH = reinterpret_cast<float*>(smem) + HID * NCLS;    // [16][512]

        for (int idx = tid; idx < HID * NCLS; idx += NTHREADS)
            sP[idx] = Wph[idx];
        const float* hf = &g_h[SEQ_LEN & 1][0][0];
        for (int idx = tid; idx < TILE_R * HID; idx += NTHREADS) {
            int r = idx >> 9;
            int k = idx & 511;
            sH[r * HID + k] = __ldcv(hf + (r0 + r) * HID + k);
        }
        __syncthreads();

        for (int idx = tid; idx < TILE_R * NCLS; idx += NTHREADS) {
            int r = idx / NCLS;
            int c = idx - r * NCLS;
            float s = bp[c];
            const float* hr = sH + r * HID;
            #pragma unroll 8
            for (int k = 0; k < HID; ++k)
                s += hr[k] * sP[k * NCLS + c];
            out[(r0 + r) * NCLS + c] = s;
        }
    }
}

extern "C" void kernel_launch(void* const* d_in, const int* in_sizes, int n_in,
                              void* d_out, int out_size)
{
    const float* x   = (const float*)d_in[0];
    const float* Whx = (const float*)d_in[1];
    const float* Whh = (const float*)d_in[2];
    const float* Wph = (const float*)d_in[3];
    const float* bh  = (const float*)d_in[4];
    const float* bp  = (const float*)d_in[5];
    float* out = (float*)d_out;

    // Reset barrier + zero initial h every launch (deterministic graph replays).
    void* bar_addr = nullptr;
    void* h_addr   = nullptr;
    cudaGetSymbolAddress(&bar_addr, g_bar);
    cudaGetSymbolAddress(&h_addr, g_h);
    cudaMemsetAsync(bar_addr, 0, sizeof(unsigned));
    cudaMemsetAsync(h_addr, 0, (size_t)BATCH * HID * sizeof(float));

    cudaFuncSetAttribute(rnn_persistent_kernel,
                         cudaFuncAttributeMaxDynamicSharedMemorySize, SMEM_BYTES);

    rnn_persistent_kernel<<<GRID_DIM, NTHREADS, SMEM_BYTES>>>(
        x, Whx, Whh, Wph, bh, bp, out);
}